// round 1
// baseline (speedup 1.0000x reference)
#include <cuda_runtime.h>
#include <cuda_bf16.h>
#include <cstddef>

// Problem constants
#define NCH 16
#define ND  64
#define NH  96
#define NW  96
#define PLANE (NH*NW)            // 9216
#define CH_STRIDE (ND*NH*NW)     // 589824
#define KOUT 8

// Shared layout (floats)
// XR  : 3 * 36*37 = 3996
// A   : 36*37     = 1332
// BZ  : 36*37     = 1332
// GX/GY/GZ: 34*35 = 1190 each
// RP  : 6 * 34*33 = 6732
// RED : 512
#define OFF_XR  0
#define OFF_A   3996
#define OFF_BZ  5328
#define OFF_GX  6660
#define OFF_GY  7850
#define OFF_GZ  9040
#define OFF_RP  10230
#define OFF_RED 16962
#define SH_FLOATS 17474
#define SH_BYTES  (SH_FLOATS*4)

__device__ double g_p[NCH];
__device__ int    g_idx[KOUT];

__global__ void zero_kernel() {
    if (threadIdx.x < NCH) g_p[threadIdx.x] = 0.0;
}

__device__ __forceinline__ void load_plane(float* dst, const float* xc, int dd,
                                           int h0, int w0, int tid) {
    if (dd < 0 || dd >= ND) {
        for (int idx = tid; idx < 36*36; idx += 512)
            dst[(idx/36)*37 + (idx%36)] = 0.f;
    } else {
        const float* xp = xc + (size_t)dd * PLANE;
        for (int idx = tid; idx < 36*36; idx += 512) {
            int i = idx / 36, j = idx % 36;
            int gh = h0 + i - 2, gw = w0 + j - 2;
            float v = 0.f;
            if ((unsigned)gh < (unsigned)NH && (unsigned)gw < (unsigned)NW)
                v = xp[gh*NW + gw];
            dst[i*37 + j] = v;
        }
    }
}

__device__ __forceinline__ float harris_of(float sxx, float syy, float szz,
                                           float sxy, float sxz, float syz) {
    // box = sums / 27 ; det homogeneous deg 3, trace deg 1
    float det = sxx*(syy*szz - syz*syz)
              - sxy*(sxy*szz - syz*sxz)
              + sxz*(sxy*syz - syy*sxz);
    float tr  = sxx + syy + szz;
    const float C1 = 1.f/19683.f;       // 1/27^3
    const float C2 = 0.04f/729.f;       // k/27^2
    return det*C1 - C2*tr*tr;
}

__global__ __launch_bounds__(512) void harris_kernel(const float* __restrict__ x) {
    extern __shared__ float sh[];
    float* XR  = sh + OFF_XR;
    float* A   = sh + OFF_A;
    float* BZ  = sh + OFF_BZ;
    float* GX  = sh + OFF_GX;
    float* GY  = sh + OFF_GY;
    float* GZ  = sh + OFF_GZ;
    float* RP  = sh + OFF_RP;
    float* RED = sh + OFF_RED;

    const int tid = threadIdx.x;
    const int c   = blockIdx.z;
    const int h0  = blockIdx.y * 32;
    const int w0  = blockIdx.x * 32;
    const float* xc = x + (size_t)c * CH_STRIDE;

    const int tw = tid & 31;          // owned column 0..31
    const int r0 = (tid >> 5) * 2;    // owned rows r0, r0+1

    // depth ring of 2D-boxed structure tensor sums: [pixel][6]
    float p1[12], p2[12];
#pragma unroll
    for (int i = 0; i < 12; i++) { p1[i] = 0.f; p2[i] = 0.f; }
    float hsum = 0.f;

    // preload x(-1) -> slot 2 (zeros), x(0) -> slot 0
    load_plane(XR + 2*1332, xc, -1, h0, w0, tid);
    load_plane(XR + 0*1332, xc,  0, h0, w0, tid);

    for (int dd = 0; dd < ND; dd++) {
        load_plane(XR + ((dd+1)%3)*1332, xc, dd+1, h0, w0, tid);
        __syncthreads();

        const float* xm = XR + ((dd+2)%3)*1332;   // d-1
        const float* x0 = XR + ((dd  )%3)*1332;   // d
        const float* xp = XR + ((dd+1)%3)*1332;   // d+1

        // A = xm + x0 + xp ; Bz = xp - xm   over 36x36
        for (int idx = tid; idx < 36*36; idx += 512) {
            int i = idx/36, j = idx%36, o = i*37+j;
            float m = xm[o], z = x0[o], p = xp[o];
            A[o]  = m + z + p;
            BZ[o] = p - m;
        }
        __syncthreads();

        // gradients over 34x34 (grad (i,j) <-> global (h0+i-1, w0+j-1))
        for (int idx = tid; idx < 34*34; idx += 512) {
            int i = idx/34, j = idx%34;
            int b = i*37 + j;
            float a00 = A[b],    a01 = A[b+1],  a02 = A[b+2];
            float a10 = A[b+37],               a12 = A[b+39];
            float a20 = A[b+74], a21 = A[b+75], a22 = A[b+76];
            float gx = (a02 - a00) + 2.f*(a12 - a10) + (a22 - a20);
            float gy = (a20 + 2.f*a21 + a22) - (a00 + 2.f*a01 + a02);
            float gz = BZ[b] + BZ[b+1] + BZ[b+2]
                     + BZ[b+37] + BZ[b+38] + BZ[b+39]
                     + BZ[b+74] + BZ[b+75] + BZ[b+76];
            int go = i*35 + j;
            GX[go] = gx; GY[go] = gy; GZ[go] = gz;
        }
        __syncthreads();

        // row-filtered products: rp rows 0..33, cols 0..31
        for (int idx = tid; idx < 34*32; idx += 512) {
            int i = idx >> 5, j = idx & 31;
            int b = i*35 + j;
            float sxx=0.f, syy=0.f, szz=0.f, sxy=0.f, sxz=0.f, syz=0.f;
#pragma unroll
            for (int t = 0; t < 3; t++) {
                float X = GX[b+t], Y = GY[b+t], Z = GZ[b+t];
                sxx = fmaf(X,X,sxx); syy = fmaf(Y,Y,syy); szz = fmaf(Z,Z,szz);
                sxy = fmaf(X,Y,sxy); sxz = fmaf(X,Z,sxz); syz = fmaf(Y,Z,syz);
            }
            int ro = i*33 + j;
            RP[        ro] = sxx; RP[1122 + ro] = syy; RP[2244 + ro] = szz;
            RP[3366 + ro] = sxy; RP[4488 + ro] = sxz; RP[5610 + ro] = syz;
        }
        __syncthreads();

        // vertical 3-tap (2D box complete for depth dd) + depth ring + harris
        float cur[12];
        {
            int base = r0*33 + tw;
#pragma unroll
            for (int p = 0; p < 6; p++) {
                const float* rp = RP + p*1122;
                float v0 = rp[base], v1 = rp[base+33], v2 = rp[base+66], v3 = rp[base+99];
                cur[p]   = v0 + v1 + v2;
                cur[6+p] = v1 + v2 + v3;
            }
        }
        if (dd >= 1) {
#pragma unroll
            for (int px = 0; px < 2; px++) {
                float S0 = p2[px*6+0] + p1[px*6+0] + cur[px*6+0];
                float S1 = p2[px*6+1] + p1[px*6+1] + cur[px*6+1];
                float S2 = p2[px*6+2] + p1[px*6+2] + cur[px*6+2];
                float S3 = p2[px*6+3] + p1[px*6+3] + cur[px*6+3];
                float S4 = p2[px*6+4] + p1[px*6+4] + cur[px*6+4];
                float S5 = p2[px*6+5] + p1[px*6+5] + cur[px*6+5];
                hsum += harris_of(S0,S1,S2,S3,S4,S5);
            }
        }
#pragma unroll
        for (int i = 0; i < 12; i++) { p2[i] = p1[i]; p1[i] = cur[i]; }
        // no extra sync needed: next-iteration RP writes are separated by 3 syncs
    }
    // final output depth d = 63: bp2d(64) == 0
#pragma unroll
    for (int px = 0; px < 2; px++) {
        float S0 = p2[px*6+0] + p1[px*6+0];
        float S1 = p2[px*6+1] + p1[px*6+1];
        float S2 = p2[px*6+2] + p1[px*6+2];
        float S3 = p2[px*6+3] + p1[px*6+3];
        float S4 = p2[px*6+4] + p1[px*6+4];
        float S5 = p2[px*6+5] + p1[px*6+5];
        hsum += harris_of(S0,S1,S2,S3,S4,S5);
    }

    // block reduction
    RED[tid] = hsum;
    __syncthreads();
    for (int s = 256; s > 0; s >>= 1) {
        if (tid < s) RED[tid] += RED[tid + s];
        __syncthreads();
    }
    if (tid == 0) atomicAdd(&g_p[c], (double)RED[0]);
}

__global__ void topk_kernel() {
    if (threadIdx.x == 0 && blockIdx.x == 0) {
        double v[NCH];
        bool used[NCH];
        for (int i = 0; i < NCH; i++) { v[i] = g_p[i]; used[i] = false; }
        for (int k = 0; k < KOUT; k++) {
            int bi = 0; double bv = -1e300; bool found = false;
            for (int i = 0; i < NCH; i++) {
                if (!used[i] && (!found || v[i] > bv)) { bv = v[i]; bi = i; found = true; }
            }
            used[bi] = true;
            g_idx[k] = bi;
        }
    }
}

__global__ void gather_kernel(const float* __restrict__ x, float* __restrict__ out) {
    int tid = blockIdx.x * blockDim.x + threadIdx.x;
    const int per_ch = CH_STRIDE / 4;       // float4 per channel = 147456
    const int total  = KOUT * per_ch;       // 1179648
    if (tid < total) {
        int k = tid / per_ch;
        int r = tid - k * per_ch;
        int c = g_idx[k];
        const float4* src = reinterpret_cast<const float4*>(x + (size_t)c * CH_STRIDE);
        reinterpret_cast<float4*>(out)[tid] = src[r];
    }
}

extern "C" void kernel_launch(void* const* d_in, const int* in_sizes, int n_in,
                              void* d_out, int out_size) {
    const float* x = (const float*)d_in[0];
    float* out = (float*)d_out;

    cudaFuncSetAttribute(harris_kernel,
                         cudaFuncAttributeMaxDynamicSharedMemorySize, SH_BYTES);

    zero_kernel<<<1, 32>>>();
    dim3 grid(3, 3, NCH);
    harris_kernel<<<grid, 512, SH_BYTES>>>(x);
    topk_kernel<<<1, 1>>>();
    const int total_vec = KOUT * (CH_STRIDE / 4);
    gather_kernel<<<(total_vec + 255) / 256, 256>>>(x, out);
}

// round 2
// speedup vs baseline: 1.5934x; 1.5934x over previous
#include <cuda_runtime.h>
#include <cuda_bf16.h>
#include <cstddef>

// Problem constants
#define NCH 16
#define ND  64
#define NH  96
#define NW  96
#define PLANE (NH*NW)            // 9216
#define CH_STRIDE (ND*NH*NW)     // 589824
#define KOUT 8

// Shared layout (floats)
// A   : 36*37 = 1332           @ 0
// BZ  : 36*37 = 1332           @ 1332
// GX/GY/GZ : 34*35 = 1190 each @ 2664 / 3854 / 5044
// RP (3 float2 arrays, 34*33 float2 each = 2244 floats each) @ 6234
// RED : 32                     @ 12966
#define OFF_A   0
#define OFF_BZ  1332
#define OFF_GX  2664
#define OFF_GY  3854
#define OFF_GZ  5044
#define OFF_RP  6234
#define OFF_RED 12966
#define SH_FLOATS 13000
#define SH_BYTES  (SH_FLOATS*4)

#define RP_F2_PER_ARR 1122   // 34*33 float2

__device__ double g_p[NCH];
__device__ int    g_idx[KOUT];

__global__ void zero_kernel() {
    if (threadIdx.x < NCH) g_p[threadIdx.x] = 0.0;
}

__device__ __forceinline__ float harris_of(float sxx, float syy, float szz,
                                           float sxy, float sxz, float syz) {
    float det = sxx*(syy*szz - syz*syz)
              - sxy*(sxy*szz - syz*sxz)
              + sxz*(sxy*syz - syy*sxz);
    float tr  = sxx + syy + szz;
    const float C1 = 1.f/19683.f;       // 1/27^3
    const float C2 = 0.04f/729.f;       // k/27^2
    return det*C1 - C2*tr*tr;
}

__global__ __launch_bounds__(512, 2) void harris_kernel(const float* __restrict__ x) {
    extern __shared__ float sh[];
    float*  A   = sh + OFF_A;
    float*  BZ  = sh + OFF_BZ;
    float*  GX  = sh + OFF_GX;
    float*  GY  = sh + OFF_GY;
    float*  GZ  = sh + OFF_GZ;
    float2* RPa = reinterpret_cast<float2*>(sh + OFF_RP);
    float2* RPb = RPa + RP_F2_PER_ARR;
    float2* RPc = RPb + RP_F2_PER_ARR;
    float*  RED = sh + OFF_RED;

    const int tid = threadIdx.x;
    const int c   = blockIdx.z >> 1;
    const int zhalf = blockIdx.z & 1;
    const int h0  = blockIdx.y * 32;
    const int w0  = blockIdx.x * 32;
    const float* xc = x + (size_t)c * CH_STRIDE;

    const int z0 = zhalf * 32;
    const int z1 = z0 + 32;
    const int s_begin = (z0 == 0) ? 0 : z0 - 1;
    const int s_end   = (z1 == ND) ? ND - 1 : z1;   // inclusive

    // ---- per-thread owned pixels of the 36x36 extended grid (up to 3) ----
    int offs[3];   // global plane offset or -1 (zero pad)
    int sto[3];    // shared store offset (i*37+j) or -1 (no pixel)
#pragma unroll
    for (int k = 0; k < 3; k++) {
        int idx = tid + k * 512;
        if (idx < 36*36) {
            int i = idx / 36, j = idx % 36;
            sto[k] = i*37 + j;
            int gh = h0 + i - 2, gw = w0 + j - 2;
            offs[k] = ((unsigned)gh < (unsigned)NH && (unsigned)gw < (unsigned)NW)
                      ? gh*NW + gw : -1;
        } else { sto[k] = -1; offs[k] = -1; }
    }

    // x-depth ring in registers
    float xm[3], x0r[3];
#pragma unroll
    for (int k = 0; k < 3; k++) {
        xm[k] = 0.f; x0r[k] = 0.f;
        if (sto[k] >= 0 && offs[k] >= 0) {
            if (s_begin - 1 >= 0) xm[k]  = xc[(size_t)(s_begin-1)*PLANE + offs[k]];
            x0r[k] = xc[(size_t)s_begin*PLANE + offs[k]];
        }
    }

    // stage-4 ownership: 2 output pixels per thread
    const int tw = tid & 31;
    const int r0 = (tid >> 5) * 2;
    const int base4 = r0*33 + tw;

    // depth running sums: A1 = slice(s), A2 = slice(s-1)+slice(s)  [after update]
    float A1[12], A2[12];
#pragma unroll
    for (int i = 0; i < 12; i++) { A1[i] = 0.f; A2[i] = 0.f; }
    float hsum = 0.f;

    for (int s = s_begin; s <= s_end; s++) {
        // ---- stage 1: load x(s+1), write A / BZ ----
        int sp = s + 1;
#pragma unroll
        for (int k = 0; k < 3; k++) {
            if (sto[k] >= 0) {
                float xpv = 0.f;
                if (offs[k] >= 0 && sp < ND)
                    xpv = xc[(size_t)sp*PLANE + offs[k]];
                A [sto[k]] = xm[k] + x0r[k] + xpv;
                BZ[sto[k]] = xpv - xm[k];
                xm[k] = x0r[k]; x0r[k] = xpv;
            }
        }
        __syncthreads();

        // ---- stage 2: gradients, vertical pairs (17 row-pairs x 34 cols) ----
        for (int idx = tid; idx < 17*34; idx += 512) {
            int pi = idx / 34, j = idx % 34;
            int i0 = pi * 2;
            int b = i0*37 + j;
            // 4 rows of A and BZ, cols j..j+2
            float hd[4], h121[4], rs[4];
#pragma unroll
            for (int r = 0; r < 4; r++) {
                int o = b + r*37;
                float a0 = A[o], a1 = A[o+1], a2 = A[o+2];
                hd[r]   = a2 - a0;
                h121[r] = a0 + 2.f*a1 + a2;
                rs[r]   = BZ[o] + BZ[o+1] + BZ[o+2];
            }
            int go = i0*35 + j;
            GX[go]      = hd[0] + 2.f*hd[1] + hd[2];
            GX[go+35]   = hd[1] + 2.f*hd[2] + hd[3];
            GY[go]      = h121[2] - h121[0];
            GY[go+35]   = h121[3] - h121[1];
            GZ[go]      = rs[0] + rs[1] + rs[2];
            GZ[go+35]   = rs[1] + rs[2] + rs[3];
        }
        __syncthreads();

        // ---- stage 3: row-summed products -> float2-packed RP ----
        for (int idx = tid; idx < 34*32; idx += 512) {
            int i = idx >> 5, j = idx & 31;
            int b = i*35 + j;
            float sxx=0.f, syy=0.f, szz=0.f, sxy=0.f, sxz=0.f, syz=0.f;
#pragma unroll
            for (int t = 0; t < 3; t++) {
                float X = GX[b+t], Y = GY[b+t], Z = GZ[b+t];
                sxx = fmaf(X,X,sxx); syy = fmaf(Y,Y,syy); szz = fmaf(Z,Z,szz);
                sxy = fmaf(X,Y,sxy); sxz = fmaf(X,Z,sxz); syz = fmaf(Y,Z,syz);
            }
            int ro = i*33 + j;
            RPa[ro] = make_float2(sxx, syy);
            RPb[ro] = make_float2(szz, sxy);
            RPc[ro] = make_float2(sxz, syz);
        }
        __syncthreads();

        // ---- stage 4: vertical 3-tap + depth accumulation + harris ----
        float2 a0 = RPa[base4], a1 = RPa[base4+33], a2 = RPa[base4+66], a3 = RPa[base4+99];
        float2 b0 = RPb[base4], b1 = RPb[base4+33], b2 = RPb[base4+66], b3 = RPb[base4+99];
        float2 c0 = RPc[base4], c1 = RPc[base4+33], c2 = RPc[base4+66], c3 = RPc[base4+99];

        float cur[12];
        cur[0]  = a0.x + a1.x + a2.x;  // sxx px0
        cur[1]  = a0.y + a1.y + a2.y;  // syy
        cur[2]  = b0.x + b1.x + b2.x;  // szz
        cur[3]  = b0.y + b1.y + b2.y;  // sxy
        cur[4]  = c0.x + c1.x + c2.x;  // sxz
        cur[5]  = c0.y + c1.y + c2.y;  // syz
        cur[6]  = a1.x + a2.x + a3.x;  // px1
        cur[7]  = a1.y + a2.y + a3.y;
        cur[8]  = b1.x + b2.x + b3.x;
        cur[9]  = b1.y + b2.y + b3.y;
        cur[10] = c1.x + c2.x + c3.x;
        cur[11] = c1.y + c2.y + c3.y;

        int d = s - 1;
        if (d >= z0 && d < z1) {
#pragma unroll
            for (int px = 0; px < 2; px++) {
                hsum += harris_of(A2[px*6+0] + cur[px*6+0],
                                  A2[px*6+1] + cur[px*6+1],
                                  A2[px*6+2] + cur[px*6+2],
                                  A2[px*6+3] + cur[px*6+3],
                                  A2[px*6+4] + cur[px*6+4],
                                  A2[px*6+5] + cur[px*6+5]);
            }
        }
#pragma unroll
        for (int i = 0; i < 12; i++) { A2[i] = A1[i] + cur[i]; A1[i] = cur[i]; }
    }

    // tail: output depth ND-1 uses zero slice at ND
    if (z1 == ND) {
#pragma unroll
        for (int px = 0; px < 2; px++) {
            hsum += harris_of(A2[px*6+0], A2[px*6+1], A2[px*6+2],
                              A2[px*6+3], A2[px*6+4], A2[px*6+5]);
        }
    }

    // ---- reduction: warp shuffle, then cross-warp via shared ----
#pragma unroll
    for (int o = 16; o > 0; o >>= 1)
        hsum += __shfl_down_sync(0xffffffffu, hsum, o);
    if ((tid & 31) == 0) RED[tid >> 5] = hsum;
    __syncthreads();
    if (tid < 32) {
        float v = (tid < 16) ? RED[tid] : 0.f;
#pragma unroll
        for (int o = 8; o > 0; o >>= 1)
            v += __shfl_down_sync(0xffffffffu, v, o);
        if (tid == 0) atomicAdd(&g_p[c], (double)v);
    }
}

__global__ void topk_kernel() {
    if (threadIdx.x == 0 && blockIdx.x == 0) {
        double v[NCH];
        bool used[NCH];
        for (int i = 0; i < NCH; i++) { v[i] = g_p[i]; used[i] = false; }
        for (int k = 0; k < KOUT; k++) {
            int bi = 0; double bv = -1e300; bool found = false;
            for (int i = 0; i < NCH; i++) {
                if (!used[i] && (!found || v[i] > bv)) { bv = v[i]; bi = i; found = true; }
            }
            used[bi] = true;
            g_idx[k] = bi;
        }
    }
}

// MLP-4 gather: each thread moves 4 float4, block covers a 1024-float4 chunk.
// per_ch = 147456 float4, divisible by 1024 -> channel constant per block.
__global__ __launch_bounds__(256) void gather_kernel(const float* __restrict__ x,
                                                     float* __restrict__ out) {
    const int per_ch_v = CH_STRIDE / 4;          // 147456
    const int chunks_per_ch = per_ch_v / 1024;   // 144
    int k = blockIdx.x / chunks_per_ch;
    int chunk = blockIdx.x - k * chunks_per_ch;
    int c = g_idx[k];
    const float4* src = reinterpret_cast<const float4*>(x + (size_t)c * CH_STRIDE);
    float4* dst = reinterpret_cast<float4*>(out) + (size_t)k * per_ch_v;
    int base = chunk * 1024 + threadIdx.x;
    float4 v0 = src[base];
    float4 v1 = src[base + 256];
    float4 v2 = src[base + 512];
    float4 v3 = src[base + 768];
    dst[base]       = v0;
    dst[base + 256] = v1;
    dst[base + 512] = v2;
    dst[base + 768] = v3;
}

extern "C" void kernel_launch(void* const* d_in, const int* in_sizes, int n_in,
                              void* d_out, int out_size) {
    const float* x = (const float*)d_in[0];
    float* out = (float*)d_out;

    cudaFuncSetAttribute(harris_kernel,
                         cudaFuncAttributeMaxDynamicSharedMemorySize, SH_BYTES);

    zero_kernel<<<1, 32>>>();
    dim3 grid(3, 3, NCH * 2);
    harris_kernel<<<grid, 512, SH_BYTES>>>(x);
    topk_kernel<<<1, 1>>>();
    const int gather_blocks = KOUT * ((CH_STRIDE / 4) / 1024);  // 8*144 = 1152
    gather_kernel<<<gather_blocks, 256>>>(x, out);
}